// round 15
// baseline (speedup 1.0000x reference)
#include <cuda_runtime.h>
#include <cuda_bf16.h>

#define IW 1024
#define IH 1024
#define NB 16
#define NC 6
#define ROWS 4
#define PLANE (IW * IH)

// Load a 6-wide window (x4-1 .. x4+4) directly: 1 float4 + 2 guarded scalars.
// No shuffles: the scalar halos hit L1 (same lines as neighbor lanes' float4s).
__device__ __forceinline__ void loadwin(const float* __restrict__ plane,
                                        int y, int x4, float* w) {
    if ((unsigned)y < IH) {
        const float* p = plane + (size_t)y * IW + x4;
        float4 v = *reinterpret_cast<const float4*>(p);
        w[0] = (x4 > 0) ? p[-1] : 0.0f;
        w[1] = v.x; w[2] = v.y; w[3] = v.z; w[4] = v.w;
        w[5] = (x4 + 4 < IW) ? p[4] : 0.0f;
    } else {
        w[0] = w[1] = w[2] = w[3] = w[4] = w[5] = 0.0f;
    }
}

__global__ __launch_bounds__(256, 3)
void fire_strip_pipe(const float* __restrict__ x, float* __restrict__ out) {
    const int bid = blockIdx.x;
    const int b = bid >> 8;                 // / (IH/ROWS)
    const int ys = (bid & 255) * ROWS;
    const int x4 = threadIdx.x * 4;

    const float* basep = x + (size_t)b * NC * PLANE;
    const float* elev = basep;
    const float* fire = basep + 5 * PLANE;
    float* outp = out + (size_t)b * PLANE;

    float eU[6], eM[6], eD[6], nE[6];
    float fU[6], fM[6], fD[6], nF[6];

    // ---- prologue: rows ys-1, ys, ys+1 + prefetch ys+2 ----
    loadwin(elev, ys - 1, x4, eU);
    loadwin(elev, ys,     x4, eM);
    loadwin(elev, ys + 1, x4, eD);
    loadwin(fire, ys - 1, x4, fU);
    loadwin(fire, ys,     x4, fM);
    loadwin(fire, ys + 1, x4, fD);
    loadwin(elev, ys + 2, x4, nE);
    loadwin(fire, ys + 2, x4, nF);

    const float R = 0.70710678118654752f;
    const float DEG2RAD = 0.017453292519943295f;

    #pragma unroll
    for (int r = 0; r < ROWS; r++) {
        const int y = ys + r;
        const size_t ro = (size_t)y * IW + x4;

        // channel loads for THIS row (consumed ~40+ instructions below;
        // cross-warp interleave covers the remaining latency)
        float4 ws4 = *reinterpret_cast<const float4*>(basep + 1 * PLANE + ro);
        float4 wd4 = *reinterpret_cast<const float4*>(basep + 2 * PLANE + ro);
        float4 hu4 = *reinterpret_cast<const float4*>(basep + 3 * PLANE + ro);
        float4 nd4 = *reinterpret_cast<const float4*>(basep + 4 * PLANE + ro);

        float wsa[4] = {ws4.x, ws4.y, ws4.z, ws4.w};
        float wda[4] = {wd4.x, wd4.y, wd4.z, wd4.w};
        float hua[4] = {hu4.x, hu4.y, hu4.z, hu4.w};
        float nda[4] = {nd4.x, nd4.y, nd4.z, nd4.w};

        // compute row y from eU/eM/eD, fU/fM/fD (loaded >= 1 iteration ago,
        // except iteration 0 which eats the startup latency once)
        float o[4];
        #pragma unroll
        for (int j = 0; j < 4; j++) {
            float dxv = ((eU[j + 2] - eU[j]) + 2.0f * (eM[j + 2] - eM[j])
                        + (eD[j + 2] - eD[j])) * 0.125f;
            float dyv = ((eD[j] - eU[j]) + 2.0f * (eD[j + 1] - eU[j + 1])
                        + (eD[j + 2] - eU[j + 2])) * 0.125f;
            float v = dxv * dxv + dyv * dyv + 1e-8f;
            float g = v * rsqrtf(v);              // sqrt(v)
            float slope_eff = 1.0f + 0.078f * g;  // tan(atan(g)) == g
            float md = fminf(fmaxf(1.0f - 400.0f * hua[j], 0.3f), 1.0f);
            float veg = 0.5f + 0.5f * fminf(fmaxf(nda[j], 0.0f), 1.0f);
            float base = 0.58f * slope_eff * md * veg;

            // wm = (270 - wd) deg; t = wd*pi/180 in [0, 0.01745)
            float t = wda[j] * DEG2RAD;
            float t2 = t * t;
            float sw = 0.5f * t2 - 1.0f;                  // sin(wm) = -cos t
            float cw = t * (t2 * (1.0f / 6.0f) - 1.0f);   // cos(wm) = -sin t
            float c_pcs = R * (cw + sw);
            float c_mcs = R * (cw - sw);

            float m = -2.0f;
            m = (fU[j + 1] > 0.5f) ? fmaxf(m,  sw)    : m;   // (-1, 0)
            m = (fU[j + 2] > 0.5f) ? fmaxf(m,  c_pcs) : m;   // (-1, 1)
            m = (fM[j + 2] > 0.5f) ? fmaxf(m,  cw)    : m;   // ( 0, 1)
            m = (fD[j + 2] > 0.5f) ? fmaxf(m,  c_mcs) : m;   // ( 1, 1)
            m = (fD[j + 1] > 0.5f) ? fmaxf(m, -sw)    : m;   // ( 1, 0)
            m = (fD[j]     > 0.5f) ? fmaxf(m, -c_pcs) : m;   // ( 1,-1)
            m = (fM[j]     > 0.5f) ? fmaxf(m, -cw)    : m;   // ( 0,-1)
            m = (fU[j]     > 0.5f) ? fmaxf(m, -c_mcs) : m;   // (-1,-1)

            // clip(base*wf,0,1) is a no-op: base in (0,0.62], wf in [0.955,1.045]
            float wf = 1.0f + 0.045f * m * wsa[j];
            float prob = (m >= -1.0f) ? base * wf : 0.0f;

            float fsv = fM[j + 1];
            o[j] = fmaxf(fsv, (fsv < 0.5f) ? prob : 0.0f);
        }

        *reinterpret_cast<float4*>(outp + ro) =
            make_float4(o[0], o[1], o[2], o[3]);

        // roll windows (register renaming under unroll) and prefetch row y+3,
        // consumed 2 iterations from now.
        if (r < ROWS - 1) {
            #pragma unroll
            for (int k = 0; k < 6; k++) {
                eU[k] = eM[k]; eM[k] = eD[k]; eD[k] = nE[k];
                fU[k] = fM[k]; fM[k] = fD[k]; fD[k] = nF[k];
            }
            if (r < ROWS - 2) {
                loadwin(elev, y + 3, x4, nE);
                loadwin(fire, y + 3, x4, nF);
            }
        }
    }
}

extern "C" void kernel_launch(void* const* d_in, const int* in_sizes, int n_in,
                              void* d_out, int out_size) {
    (void)in_sizes; (void)n_in; (void)out_size;
    const float* x = (const float*)d_in[0];
    float* out = (float*)d_out;
    fire_strip_pipe<<<NB * (IH / ROWS), 256>>>(x, out);
}

// round 16
// speedup vs baseline: 1.1686x; 1.1686x over previous
#include <cuda_runtime.h>
#include <cuda_bf16.h>

#define IW 1024
#define IH 1024
#define NB 16
#define NC 6
#define PLANE (IW * IH)
#define FULLMASK 0xffffffffu

__global__ __launch_bounds__(128)
void fire_spread_flat(const float* __restrict__ x, float* __restrict__ out) {
    const int bid = blockIdx.x;
    // 2 blocks per row: seg selects left/right 512-px half
    const int seg = bid & 1;
    const int y = (bid >> 1) & (IH - 1);
    const int b = bid >> 11;
    const int tx = threadIdx.x;
    const int x4 = seg * 512 + tx * 4;
    const int lane = tx & 31;

    const float* basep = x + (size_t)b * NC * PLANE;
    const size_t rowoff = (size_t)y * IW + x4;
    const float* pEC = basep + rowoff;                 // elev, row y
    const float* pFC = basep + 5 * PLANE + rowoff;     // fire, row y

    const bool vP = (y > 0);
    const bool vN = (y < IH - 1);

    const float4 z4 = make_float4(0.f, 0.f, 0.f, 0.f);

    // ---- front-batch all 10 float4 loads (max MLP) ----
    float4 ePv = vP ? *reinterpret_cast<const float4*>(pEC - IW) : z4;
    float4 eCv =      *reinterpret_cast<const float4*>(pEC);
    float4 eNv = vN ? *reinterpret_cast<const float4*>(pEC + IW) : z4;
    float4 fPv = vP ? *reinterpret_cast<const float4*>(pFC - IW) : z4;
    float4 fCv =      *reinterpret_cast<const float4*>(pFC);
    float4 fNv = vN ? *reinterpret_cast<const float4*>(pFC + IW) : z4;
    float4 ws4 = *reinterpret_cast<const float4*>(basep + 1 * PLANE + rowoff);
    float4 wd4 = *reinterpret_cast<const float4*>(basep + 2 * PLANE + rowoff);
    float4 hu4 = *reinterpret_cast<const float4*>(basep + 3 * PLANE + rowoff);
    float4 nd4 = *reinterpret_cast<const float4*>(basep + 4 * PLANE + rowoff);

    // ---- halo exchange via shuffles ----
    float lEP = __shfl_up_sync(FULLMASK, ePv.w, 1);
    float lEC = __shfl_up_sync(FULLMASK, eCv.w, 1);
    float lEN = __shfl_up_sync(FULLMASK, eNv.w, 1);
    float lFP = __shfl_up_sync(FULLMASK, fPv.w, 1);
    float lFC = __shfl_up_sync(FULLMASK, fCv.w, 1);
    float lFN = __shfl_up_sync(FULLMASK, fNv.w, 1);
    float rEP = __shfl_down_sync(FULLMASK, ePv.x, 1);
    float rEC = __shfl_down_sync(FULLMASK, eCv.x, 1);
    float rEN = __shfl_down_sync(FULLMASK, eNv.x, 1);
    float rFP = __shfl_down_sync(FULLMASK, fPv.x, 1);
    float rFC = __shfl_down_sync(FULLMASK, fCv.x, 1);
    float rFN = __shfl_down_sync(FULLMASK, fNv.x, 1);

    if (lane == 0) {
        bool ok = (x4 > 0);
        lEP = (ok && vP) ? pEC[-IW - 1] : 0.f;
        lEC =  ok        ? pEC[-1]      : 0.f;
        lEN = (ok && vN) ? pEC[IW - 1]  : 0.f;
        lFP = (ok && vP) ? pFC[-IW - 1] : 0.f;
        lFC =  ok        ? pFC[-1]      : 0.f;
        lFN = (ok && vN) ? pFC[IW - 1]  : 0.f;
    }
    if (lane == 31) {
        bool ok = (x4 + 4 < IW);
        rEP = (ok && vP) ? pEC[-IW + 4] : 0.f;
        rEC =  ok        ? pEC[4]       : 0.f;
        rEN = (ok && vN) ? pEC[IW + 4]  : 0.f;
        rFP = (ok && vP) ? pFC[-IW + 4] : 0.f;
        rFC =  ok        ? pFC[4]       : 0.f;
        rFN = (ok && vN) ? pFC[IW + 4]  : 0.f;
    }

    float eP[6], eC[6], eN[6], fP[6], fC[6], fN[6];
    eP[0]=lEP; eP[1]=ePv.x; eP[2]=ePv.y; eP[3]=ePv.z; eP[4]=ePv.w; eP[5]=rEP;
    eC[0]=lEC; eC[1]=eCv.x; eC[2]=eCv.y; eC[3]=eCv.z; eC[4]=eCv.w; eC[5]=rEC;
    eN[0]=lEN; eN[1]=eNv.x; eN[2]=eNv.y; eN[3]=eNv.z; eN[4]=eNv.w; eN[5]=rEN;
    fP[0]=lFP; fP[1]=fPv.x; fP[2]=fPv.y; fP[3]=fPv.z; fP[4]=fPv.w; fP[5]=rFP;
    fC[0]=lFC; fC[1]=fCv.x; fC[2]=fCv.y; fC[3]=fCv.z; fC[4]=fCv.w; fC[5]=rFC;
    fN[0]=lFN; fN[1]=fNv.x; fN[2]=fNv.y; fN[3]=fNv.z; fN[4]=fNv.w; fN[5]=rFN;

    float wsa[4] = {ws4.x, ws4.y, ws4.z, ws4.w};
    float wda[4] = {wd4.x, wd4.y, wd4.z, wd4.w};
    float hua[4] = {hu4.x, hu4.y, hu4.z, hu4.w};
    float nda[4] = {nd4.x, nd4.y, nd4.z, nd4.w};

    const float R = 0.70710678118654752f;
    const float DEG2RAD = 0.017453292519943295f;

    float o[4];
    #pragma unroll
    for (int j = 0; j < 4; j++) {
        // Sobel (cross-correlation, /8), zero padded
        float dxv = ((eP[j + 2] - eP[j]) + 2.0f * (eC[j + 2] - eC[j])
                    + (eN[j + 2] - eN[j])) * 0.125f;
        float dyv = ((eN[j] - eP[j]) + 2.0f * (eN[j + 1] - eP[j + 1])
                    + (eN[j + 2] - eP[j + 2])) * 0.125f;
        float v = dxv * dxv + dyv * dyv + 1e-8f;
        float g = v * rsqrtf(v);              // sqrt(v), 1 MUFU
        float slope_eff = 1.0f + 0.078f * g;  // tan(atan(g)) == g
        float md = fminf(fmaxf(1.0f - 400.0f * hua[j], 0.3f), 1.0f);
        float veg = 0.5f + 0.5f * fminf(fmaxf(nda[j], 0.0f), 1.0f);
        float base = 0.58f * slope_eff * md * veg;

        // wm = (270 - wd) deg; t = wd*pi/180 in [0, 0.01745)
        // sin(wm) = -cos t ~= t^2/2 - 1 ; cos(wm) = -sin t ~= t*(t^2/6 - 1)
        float t = wda[j] * DEG2RAD;
        float t2 = t * t;
        float sw = 0.5f * t2 - 1.0f;
        float cw = t * (t2 * (1.0f / 6.0f) - 1.0f);

        // max cos(angle_diff) over burning neighbors; -2 sentinel = none
        float m = -2.0f;
        float c_pcs = R * (cw + sw);   // 45 / 225
        float c_mcs = R * (cw - sw);   // 315 (and -c_mcs = 135)
        m = (fP[j + 1] > 0.5f) ? fmaxf(m,  sw)    : m;   // (-1, 0)  90
        m = (fP[j + 2] > 0.5f) ? fmaxf(m,  c_pcs) : m;   // (-1, 1)  45
        m = (fC[j + 2] > 0.5f) ? fmaxf(m,  cw)    : m;   // ( 0, 1)   0
        m = (fN[j + 2] > 0.5f) ? fmaxf(m,  c_mcs) : m;   // ( 1, 1) 315
        m = (fN[j + 1] > 0.5f) ? fmaxf(m, -sw)    : m;   // ( 1, 0) 270
        m = (fN[j]     > 0.5f) ? fmaxf(m, -c_pcs) : m;   // ( 1,-1) 225
        m = (fC[j]     > 0.5f) ? fmaxf(m, -cw)    : m;   // ( 0,-1) 180
        m = (fP[j]     > 0.5f) ? fmaxf(m, -c_mcs) : m;   // (-1,-1) 135

        // clip(base*wf,0,1) is a no-op: base in (0,0.62], wf in [0.955,1.045]
        float wf = 1.0f + 0.045f * m * wsa[j];
        float prob = (m >= -1.0f) ? base * wf : 0.0f;

        float fsv = fC[j + 1];
        o[j] = fmaxf(fsv, (fsv < 0.5f) ? prob : 0.0f);
    }

    *reinterpret_cast<float4*>(out + (size_t)b * PLANE + rowoff) =
        make_float4(o[0], o[1], o[2], o[3]);
}

extern "C" void kernel_launch(void* const* d_in, const int* in_sizes, int n_in,
                              void* d_out, int out_size) {
    (void)in_sizes; (void)n_in; (void)out_size;
    const float* x = (const float*)d_in[0];
    float* out = (float*)d_out;
    fire_spread_flat<<<NB * IH * 2, 128>>>(x, out);
}